// round 1
// baseline (speedup 1.0000x reference)
#include <cuda_runtime.h>
#include <math.h>

// Shapes (fixed for this problem)
#define BB 32
#define TT 512
#define AA 64
#define DD 128
#define HH 256
#define MM (BB*TT)     // 16384 rows
#define NN (DD*DD)     // 16384 cols
#define KK HH          // 256

// Scratch: device globals (allocation-free rule)
__device__ float g_h[(size_t)MM * HH];          // 16 MB
__device__ float g_trans[(size_t)MM * NN];      // 1.07 GB

// ---------------------------------------------------------------------------
// Kernel 1: h = relu(actions @ w1 + b1)   [16384 x 64] @ [64 x 256]
// Block handles 8 rows x all 256 cols; 256 threads (one col each).
// ---------------------------------------------------------------------------
__global__ __launch_bounds__(256) void mlp1_kernel(const float* __restrict__ actions,
                                                   const float* __restrict__ w1,
                                                   const float* __restrict__ b1)
{
    __shared__ float as[8][AA];
    const int tid = threadIdx.x;
    const int m0 = blockIdx.x * 8;

    for (int i = tid; i < 8 * AA; i += 256)
        as[i >> 6][i & 63] = actions[(size_t)m0 * AA + i];
    __syncthreads();

    const int n = tid;
    float bv = b1[n];
    float acc[8];
#pragma unroll
    for (int r = 0; r < 8; r++) acc[r] = bv;

#pragma unroll 8
    for (int a = 0; a < AA; a++) {
        float w = w1[(size_t)a * HH + n];
#pragma unroll
        for (int r = 0; r < 8; r++) acc[r] = fmaf(as[r][a], w, acc[r]);
    }
#pragma unroll
    for (int r = 0; r < 8; r++)
        g_h[(size_t)(m0 + r) * HH + n] = fmaxf(acc[r], 0.0f);
}

// ---------------------------------------------------------------------------
// Kernel 2: trans = h @ w2 + b2   [16384 x 256] @ [256 x 16384]
// Classic SIMT fp32 GEMM: BM=BN=128, BK=16, 256 threads, 8x8 per-thread tile,
// double-buffered shared memory, one __syncthreads per K-tile.
// ---------------------------------------------------------------------------
__global__ __launch_bounds__(256) void gemm_kernel(const float* __restrict__ Bw,
                                                   const float* __restrict__ bias)
{
    constexpr int BM = 128, BN = 128, BK = 16;
    __shared__ float As[2][BK * BM];   // [k][m]
    __shared__ float Bs[2][BK * BN];   // [k][n]

    const int tid = threadIdx.x;
    const int m0 = blockIdx.y * BM;
    const int n0 = blockIdx.x * BN;
    const int tx = tid & 15, ty = tid >> 4;

    // A-tile load mapping: each thread loads 8 contiguous floats of one row
    const int a_row = tid >> 1;
    const int a_col = (tid & 1) * 8;
    // B-tile load mapping: each thread loads 8 contiguous floats of one k-row
    const int b_kr  = tid >> 4;
    const int b_col = (tid & 15) * 8;

    const float* Aptr = g_h + (size_t)(m0 + a_row) * KK + a_col;
    const float* Bptr = Bw + (size_t)b_kr * NN + n0 + b_col;

    float acc[8][8];
#pragma unroll
    for (int i = 0; i < 8; i++)
#pragma unroll
        for (int j = 0; j < 8; j++) acc[i][j] = 0.0f;

    // Prologue: load tile 0 into buffer 0
    float4 ra0 = *(const float4*)(Aptr);
    float4 ra1 = *(const float4*)(Aptr + 4);
    float4 rb0 = *(const float4*)(Bptr);
    float4 rb1 = *(const float4*)(Bptr + 4);
    {
        float av[8] = {ra0.x, ra0.y, ra0.z, ra0.w, ra1.x, ra1.y, ra1.z, ra1.w};
#pragma unroll
        for (int c = 0; c < 8; c++) As[0][(a_col + c) * BM + a_row] = av[c];
        *(float4*)&Bs[0][b_kr * BN + b_col] = rb0;
        *(float4*)&Bs[0][b_kr * BN + b_col + 4] = rb1;
    }
    __syncthreads();

    int buf = 0;
#pragma unroll 1
    for (int kt = 0; kt < KK / BK; kt++) {
        if (kt + 1 < KK / BK) {
            const float* Ap = Aptr + (kt + 1) * BK;
            const float* Bp = Bptr + (size_t)(kt + 1) * BK * NN;
            ra0 = *(const float4*)(Ap);
            ra1 = *(const float4*)(Ap + 4);
            rb0 = *(const float4*)(Bp);
            rb1 = *(const float4*)(Bp + 4);
        }
#pragma unroll
        for (int k = 0; k < BK; k++) {
            float ra[8], rb[8];
            *(float4*)&ra[0] = *(const float4*)&As[buf][k * BM + ty * 8];
            *(float4*)&ra[4] = *(const float4*)&As[buf][k * BM + ty * 8 + 4];
            *(float4*)&rb[0] = *(const float4*)&Bs[buf][k * BN + tx * 8];
            *(float4*)&rb[4] = *(const float4*)&Bs[buf][k * BN + tx * 8 + 4];
#pragma unroll
            for (int i = 0; i < 8; i++)
#pragma unroll
                for (int j = 0; j < 8; j++)
                    acc[i][j] = fmaf(ra[i], rb[j], acc[i][j]);
        }
        if (kt + 1 < KK / BK) {
            buf ^= 1;
            float av[8] = {ra0.x, ra0.y, ra0.z, ra0.w, ra1.x, ra1.y, ra1.z, ra1.w};
#pragma unroll
            for (int c = 0; c < 8; c++) As[buf][(a_col + c) * BM + a_row] = av[c];
            *(float4*)&Bs[buf][b_kr * BN + b_col] = rb0;
            *(float4*)&Bs[buf][b_kr * BN + b_col + 4] = rb1;
            __syncthreads();
        }
    }

    // Epilogue: add bias (broadcast over rows), store float4s
    const float4 b20 = *(const float4*)(bias + n0 + tx * 8);
    const float4 b21 = *(const float4*)(bias + n0 + tx * 8 + 4);
#pragma unroll
    for (int i = 0; i < 8; i++) {
        size_t crow = (size_t)(m0 + ty * 8 + i) * NN + n0 + tx * 8;
        float4 o0 = {acc[i][0] + b20.x, acc[i][1] + b20.y,
                     acc[i][2] + b20.z, acc[i][3] + b20.w};
        float4 o1 = {acc[i][4] + b21.x, acc[i][5] + b21.y,
                     acc[i][6] + b21.z, acc[i][7] + b21.w};
        *(float4*)(g_trans + crow) = o0;
        *(float4*)(g_trans + crow + 4) = o1;
    }
}

// ---------------------------------------------------------------------------
// Kernel 3: sequential scan over T. One CTA per batch (independent chains).
// 512 threads: c = tid>>5 selects an 8-row i-chunk, (tid&31)*4 selects 4 cols.
// Per step: y = relu(s @ Tm); s = y / max(||y||, eps); out[b,t,:] = s
// ---------------------------------------------------------------------------
__global__ __launch_bounds__(512) void scan_kernel(const float* __restrict__ init_s,
                                                   float* __restrict__ out)
{
    __shared__ float s_sm[DD];
    __shared__ float red[16][DD];
    __shared__ float wsum[16];
    __shared__ float inv_sm;

    const int tid = threadIdx.x;
    const int b = blockIdx.x;

    // s0 = l2norm(init_structure)
    if (tid < DD) {
        float v = init_s[tid];
        s_sm[tid] = v;
        red[0][tid] = v * v;
    }
    __syncthreads();
    if (tid == 0) {
        float s = 0.0f;
        for (int i = 0; i < DD; i++) s += red[0][i];
        inv_sm = 1.0f / fmaxf(sqrtf(s), 1e-12f);
    }
    __syncthreads();
    if (tid < DD) s_sm[tid] *= inv_sm;
    __syncthreads();

    const int c = tid >> 5;         // 0..15 : 8 rows each
    const int j = (tid & 31) * 4;   // 4-col group
    const float* Tb = g_trans + (size_t)b * TT * (DD * DD);

    for (int t = 0; t < TT; t++) {
        const float* Tm = Tb + (size_t)t * (DD * DD);
        float4 p = {0.0f, 0.0f, 0.0f, 0.0f};
#pragma unroll
        for (int ii = 0; ii < 8; ii++) {
            int i = c * 8 + ii;
            float sv = s_sm[i];
            float4 tv = *(const float4*)(Tm + (size_t)i * DD + j);
            p.x = fmaf(sv, tv.x, p.x);
            p.y = fmaf(sv, tv.y, p.y);
            p.z = fmaf(sv, tv.z, p.z);
            p.w = fmaf(sv, tv.w, p.w);
        }
        *(float4*)&red[c][j] = p;
        __syncthreads();

        float v = 0.0f, sq = 0.0f;
        if (tid < DD) {
#pragma unroll
            for (int cc = 0; cc < 16; cc++) v += red[cc][tid];
            v = fmaxf(v, 0.0f);
            sq = v * v;
        }
#pragma unroll
        for (int o = 16; o; o >>= 1) sq += __shfl_xor_sync(0xffffffffu, sq, o);
        if ((tid & 31) == 0) wsum[tid >> 5] = sq;
        __syncthreads();
        if (tid == 0) {
            float s = wsum[0] + wsum[1] + wsum[2] + wsum[3];
            inv_sm = 1.0f / fmaxf(sqrtf(s), 1e-12f);
        }
        __syncthreads();
        if (tid < DD) {
            float sn = v * inv_sm;
            s_sm[tid] = sn;
            out[((size_t)b * TT + t) * DD + tid] = sn;
        }
        __syncthreads();
    }
}

// ---------------------------------------------------------------------------
extern "C" void kernel_launch(void* const* d_in, const int* in_sizes, int n_in,
                              void* d_out, int out_size)
{
    const float* actions = (const float*)d_in[0];  // [32,512,64]
    const float* init_s  = (const float*)d_in[1];  // [128]
    const float* w1      = (const float*)d_in[2];  // [64,256]
    const float* b1      = (const float*)d_in[3];  // [256]
    const float* w2      = (const float*)d_in[4];  // [256,16384]
    const float* b2      = (const float*)d_in[5];  // [16384]
    float* out = (float*)d_out;                    // [32,512,128]

    mlp1_kernel<<<MM / 8, 256>>>(actions, w1, b1);
    gemm_kernel<<<dim3(NN / 128, MM / 128), 256>>>(w2, b2);
    scan_kernel<<<BB, 512>>>(init_s, out);
}

// round 3
// speedup vs baseline: 1.7881x; 1.7881x over previous
#include <cuda_runtime.h>
#include <cuda_bf16.h>
#include <math.h>
#include <stdint.h>

// Shapes (fixed)
#define BB 32
#define TT 512
#define AA 64
#define DD 128
#define HH 256
#define MM (BB*TT)     // 16384
#define NN (DD*DD)     // 16384
#define KK HH          // 256
#define KSPLIT 768     // 3*KK : A=[hi|hi|lo], B=[hi|lo|hi]

// Device scratch (allocation-free rule)
__device__ __align__(128) __nv_bfloat16 g_A2[(size_t)MM * KSPLIT];   // 25 MB
__device__ __align__(128) __nv_bfloat16 g_B2T[(size_t)NN * KSPLIT];  // 25 MB
__device__ __align__(128) float g_trans[(size_t)MM * NN];            // 1.07 GB

// ---------------------------------------------------------------------------
// PTX helpers (sm_80-class only — no tcgen05; harness targets base sm_103)
// ---------------------------------------------------------------------------
__device__ __forceinline__ uint32_t smem_u32(const void* p) {
    uint32_t a;
    asm("{ .reg .u64 t; cvta.to.shared.u64 t, %1; cvt.u32.u64 %0, t; }" : "=r"(a) : "l"(p));
    return a;
}
__device__ __forceinline__ void cp16(uint32_t dst, const void* src) {
    asm volatile("cp.async.cg.shared.global [%0], [%1], 16;" :: "r"(dst), "l"(src) : "memory");
}
__device__ __forceinline__ void cp_commit() {
    asm volatile("cp.async.commit_group;" ::: "memory");
}
template <int N>
__device__ __forceinline__ void cp_wait() {
    asm volatile("cp.async.wait_group %0;" :: "n"(N) : "memory");
}
__device__ __forceinline__ void ldsm4(uint32_t* r, uint32_t addr) {
    asm volatile("ldmatrix.sync.aligned.m8n8.x4.shared.b16 {%0,%1,%2,%3}, [%4];"
                 : "=r"(r[0]), "=r"(r[1]), "=r"(r[2]), "=r"(r[3]) : "r"(addr));
}
__device__ __forceinline__ void mma_bf16(float* d, const uint32_t* a, const uint32_t* b) {
    asm volatile(
        "mma.sync.aligned.m16n8k16.row.col.f32.bf16.bf16.f32 "
        "{%0,%1,%2,%3}, {%4,%5,%6,%7}, {%8,%9}, {%0,%1,%2,%3};"
        : "+f"(d[0]), "+f"(d[1]), "+f"(d[2]), "+f"(d[3])
        : "r"(a[0]), "r"(a[1]), "r"(a[2]), "r"(a[3]), "r"(b[0]), "r"(b[1]));
}
// SW128 swizzle, closed form for row*128+kb (kb < 128)
__device__ __forceinline__ uint32_t swoff(uint32_t row, uint32_t kb) {
    return row * 128u + (kb ^ ((row & 7u) << 4));
}

// ---------------------------------------------------------------------------
// Kernel 1: h = relu(actions@w1+b1); write A2 = [hi | hi | lo] bf16 rows
// ---------------------------------------------------------------------------
__global__ __launch_bounds__(256) void mlp1_kernel(const float* __restrict__ actions,
                                                   const float* __restrict__ w1,
                                                   const float* __restrict__ b1)
{
    __shared__ float as[8][AA];
    const int tid = threadIdx.x;
    const int m0 = blockIdx.x * 8;

    for (int i = tid; i < 8 * AA; i += 256)
        as[i >> 6][i & 63] = actions[(size_t)m0 * AA + i];
    __syncthreads();

    const int n = tid;
    float bv = b1[n];
    float acc[8];
#pragma unroll
    for (int r = 0; r < 8; r++) acc[r] = bv;
#pragma unroll 8
    for (int a = 0; a < AA; a++) {
        float w = w1[(size_t)a * HH + n];
#pragma unroll
        for (int r = 0; r < 8; r++) acc[r] = fmaf(as[r][a], w, acc[r]);
    }
#pragma unroll
    for (int r = 0; r < 8; r++) {
        float v = fmaxf(acc[r], 0.0f);
        __nv_bfloat16 hi = __float2bfloat16_rn(v);
        __nv_bfloat16 lo = __float2bfloat16_rn(v - __bfloat162float(hi));
        size_t row = (size_t)(m0 + r) * KSPLIT;
        g_A2[row + n] = hi;
        g_A2[row + KK + n] = hi;
        g_A2[row + 2 * KK + n] = lo;
    }
}

// ---------------------------------------------------------------------------
// Kernel 1b: B2T[n, :] = [hi(w2[:,n]) | lo(w2[:,n]) | hi(w2[:,n])]  (transpose)
// ---------------------------------------------------------------------------
__global__ __launch_bounds__(256) void bprep_kernel(const float* __restrict__ w2)
{
    __shared__ float tile[32][33];
    const int tx = threadIdx.x;          // 0..31
    const int ty = threadIdx.y;          // 0..7
    const int n0 = blockIdx.x * 32;
    const int k0 = blockIdx.y * 32;
#pragma unroll
    for (int i = 0; i < 4; i++) {
        int k = k0 + ty + i * 8;
        tile[ty + i * 8][tx] = w2[(size_t)k * NN + n0 + tx];
    }
    __syncthreads();
#pragma unroll
    for (int i = 0; i < 4; i++) {
        int nrow = ty + i * 8;
        float v = tile[tx][nrow];        // w2[k0+tx, n0+nrow]
        __nv_bfloat16 hi = __float2bfloat16_rn(v);
        __nv_bfloat16 lo = __float2bfloat16_rn(v - __bfloat162float(hi));
        size_t row = (size_t)(n0 + nrow) * KSPLIT + k0 + tx;
        g_B2T[row] = hi;
        g_B2T[row + KK] = lo;
        g_B2T[row + 2 * KK] = hi;
    }
}

// ---------------------------------------------------------------------------
// Kernel 2: bf16 mma.sync GEMM  trans = A2 @ B2T^T + b2
// BM=256, BN=128, BK=64 (128B rows, SW128), 3-stage cp.async, 8 warps 4x2,
// warp tile 64x64, m16n8k16 fragments via ldmatrix.x4.
// ---------------------------------------------------------------------------
#define BMG 256
#define BNG 128
#define BKG 64
#define NKT (KSPLIT/BKG)     // 12
#define NSTG 3
#define A_BYTES (BMG*128)    // 32768
#define B_BYTES (BNG*128)    // 16384
#define STAGE_BYTES (A_BYTES + B_BYTES)  // 49152

__global__ __launch_bounds__(256, 1) void gemm3_kernel(const float* __restrict__ bias)
{
    extern __shared__ char dsm[];
    __shared__ float bias_s[BNG];

    const uint32_t dyn = smem_u32(dsm);
    const int tid = threadIdx.x;
    const int wid = tid >> 5;
    const int lane = tid & 31;
    const int m0 = blockIdx.y * BMG;
    const int n0 = blockIdx.x * BNG;

    if (tid < BNG) bias_s[tid] = bias[n0 + tid];

    const char* Abase = (const char*)g_A2;
    const char* Bbase = (const char*)g_B2T;

    auto load_stage = [&](int s, int kt) {
        uint32_t sb = dyn + s * STAGE_BYTES;
        size_t kbyte = (size_t)kt * (BKG * 2);   // 128 B per k-tile
#pragma unroll
        for (int i = 0; i < 8; i++) {            // A: 2048 chunks of 16B
            int q = i * 256 + tid;
            uint32_t r = q >> 3, c = (q & 7) * 16;
            cp16(sb + swoff(r, c),
                 Abase + (size_t)(m0 + r) * (KSPLIT * 2) + kbyte + c);
        }
#pragma unroll
        for (int i = 0; i < 4; i++) {            // B: 1024 chunks
            int q = i * 256 + tid;
            uint32_t r = q >> 3, c = (q & 7) * 16;
            cp16(sb + A_BYTES + swoff(r, c),
                 Bbase + (size_t)(n0 + r) * (KSPLIT * 2) + kbyte + c);
        }
        cp_commit();
    };

    // prologue: 2 stages in flight
    load_stage(0, 0);
    load_stage(1, 1);

    // warp tiling: 4 (m) x 2 (n) warps, each 64x64
    const int m_w = (wid >> 1) * 64;
    const int n_w = (wid & 1) * 64;

    // per-lane ldmatrix row/kb components
    const uint32_t a_row = m_w + (lane & 7) + (lane & 8);          // + mi*16
    const uint32_t a_kb  = (lane >> 4) << 4;                       // + ks*32
    const uint32_t b_row = n_w + (lane & 7) + ((lane >> 4) << 3);  // + nj*16
    const uint32_t b_kb  = (lane & 8) << 1;                        // + ks*32

    float acc[4][8][4];
#pragma unroll
    for (int mi = 0; mi < 4; mi++)
#pragma unroll
        for (int nt = 0; nt < 8; nt++)
#pragma unroll
            for (int e = 0; e < 4; e++) acc[mi][nt][e] = 0.0f;

#pragma unroll 1
    for (int kt = 0; kt < NKT; kt++) {
        const int s = kt % NSTG;
        if (kt + 2 < NKT) load_stage((kt + 2) % NSTG, kt + 2);

        if (kt + 2 < NKT)      cp_wait<2>();
        else if (kt + 1 < NKT) cp_wait<1>();
        else                   cp_wait<0>();
        __syncthreads();

        const uint32_t abase = dyn + s * STAGE_BYTES;
        const uint32_t bbase = abase + A_BYTES;

#pragma unroll
        for (int ks = 0; ks < 4; ks++) {
            uint32_t af[4][4], bf[4][4];
#pragma unroll
            for (int mi = 0; mi < 4; mi++)
                ldsm4(af[mi], abase + swoff(a_row + mi * 16, a_kb + ks * 32));
#pragma unroll
            for (int nj = 0; nj < 4; nj++)
                ldsm4(bf[nj], bbase + swoff(b_row + nj * 16, b_kb + ks * 32));
#pragma unroll
            for (int mi = 0; mi < 4; mi++)
#pragma unroll
                for (int nj = 0; nj < 4; nj++) {
                    mma_bf16(acc[mi][2 * nj],     af[mi], &bf[nj][0]);
                    mma_bf16(acc[mi][2 * nj + 1], af[mi], &bf[nj][2]);
                }
        }
        __syncthreads();   // all warps done reading stage s before it is reloaded
    }

    // epilogue: direct float2 stores with bias
    const int cl = 2 * (lane & 3);
    const int rl = lane >> 2;
#pragma unroll
    for (int mi = 0; mi < 4; mi++) {
        int row0 = m0 + m_w + mi * 16 + rl;
#pragma unroll
        for (int nt = 0; nt < 8; nt++) {
            int lc = n_w + nt * 8 + cl;
            int col = n0 + lc;
            float bx = bias_s[lc], by = bias_s[lc + 1];
            float2 v0 = {acc[mi][nt][0] + bx, acc[mi][nt][1] + by};
            float2 v1 = {acc[mi][nt][2] + bx, acc[mi][nt][3] + by};
            *(float2*)(g_trans + (size_t)row0 * NN + col) = v0;
            *(float2*)(g_trans + (size_t)(row0 + 8) * NN + col) = v1;
        }
    }
}

// ---------------------------------------------------------------------------
// Kernel 3: sequential scan (unchanged)
// ---------------------------------------------------------------------------
__global__ __launch_bounds__(512) void scan_kernel(const float* __restrict__ init_s,
                                                   float* __restrict__ out)
{
    __shared__ float s_sm[DD];
    __shared__ float red[16][DD];
    __shared__ float wsum[16];
    __shared__ float inv_sm;

    const int tid = threadIdx.x;
    const int b = blockIdx.x;

    if (tid < DD) {
        float v = init_s[tid];
        s_sm[tid] = v;
        red[0][tid] = v * v;
    }
    __syncthreads();
    if (tid == 0) {
        float s = 0.0f;
        for (int i = 0; i < DD; i++) s += red[0][i];
        inv_sm = 1.0f / fmaxf(sqrtf(s), 1e-12f);
    }
    __syncthreads();
    if (tid < DD) s_sm[tid] *= inv_sm;
    __syncthreads();

    const int c = tid >> 5;
    const int j = (tid & 31) * 4;
    const float* Tb = g_trans + (size_t)b * TT * (DD * DD);

    for (int t = 0; t < TT; t++) {
        const float* Tm = Tb + (size_t)t * (DD * DD);
        float4 p = {0.0f, 0.0f, 0.0f, 0.0f};
#pragma unroll
        for (int ii = 0; ii < 8; ii++) {
            int i = c * 8 + ii;
            float sv = s_sm[i];
            float4 tv = *(const float4*)(Tm + (size_t)i * DD + j);
            p.x = fmaf(sv, tv.x, p.x);
            p.y = fmaf(sv, tv.y, p.y);
            p.z = fmaf(sv, tv.z, p.z);
            p.w = fmaf(sv, tv.w, p.w);
        }
        *(float4*)&red[c][j] = p;
        __syncthreads();

        float v = 0.0f, sq = 0.0f;
        if (tid < DD) {
#pragma unroll
            for (int cc = 0; cc < 16; cc++) v += red[cc][tid];
            v = fmaxf(v, 0.0f);
            sq = v * v;
        }
#pragma unroll
        for (int o = 16; o; o >>= 1) sq += __shfl_xor_sync(0xffffffffu, sq, o);
        if ((tid & 31) == 0) wsum[tid >> 5] = sq;
        __syncthreads();
        if (tid == 0) {
            float s = wsum[0] + wsum[1] + wsum[2] + wsum[3];
            inv_sm = 1.0f / fmaxf(sqrtf(s), 1e-12f);
        }
        __syncthreads();
        if (tid < DD) {
            float sn = v * inv_sm;
            s_sm[tid] = sn;
            out[((size_t)b * TT + t) * DD + tid] = sn;
        }
        __syncthreads();
    }
}

// ---------------------------------------------------------------------------
extern "C" void kernel_launch(void* const* d_in, const int* in_sizes, int n_in,
                              void* d_out, int out_size)
{
    const float* actions = (const float*)d_in[0];
    const float* init_s  = (const float*)d_in[1];
    const float* w1      = (const float*)d_in[2];
    const float* b1      = (const float*)d_in[3];
    const float* w2      = (const float*)d_in[4];
    const float* b2      = (const float*)d_in[5];
    float* out = (float*)d_out;

    cudaFuncSetAttribute(gemm3_kernel, cudaFuncAttributeMaxDynamicSharedMemorySize,
                         NSTG * STAGE_BYTES);

    mlp1_kernel<<<MM / 8, 256>>>(actions, w1, b1);
    bprep_kernel<<<dim3(NN / 32, KK / 32), dim3(32, 8)>>>(w2);
    gemm3_kernel<<<dim3(NN / BNG, MM / BMG), 256, NSTG * STAGE_BYTES>>>(b2);
    scan_kernel<<<BB, 512>>>(init_s, out);
}

// round 4
// speedup vs baseline: 2.4704x; 1.3816x over previous
#include <cuda_runtime.h>
#include <cuda_bf16.h>
#include <math.h>
#include <stdint.h>

// Shapes (fixed)
#define BB 32
#define TT 512
#define AA 64
#define DD 128
#define HH 256
#define MM (BB*TT)     // 16384
#define NN (DD*DD)     // 16384
#define KK HH          // 256
#define KSPLIT 768     // 3*KK : A=[hi|hi|lo], B=[hi|lo|hi]

// Device scratch (allocation-free rule)
__device__ __align__(128) __nv_bfloat16 g_A2[(size_t)MM * KSPLIT];   // 25 MB
__device__ __align__(128) __nv_bfloat16 g_B2T[(size_t)NN * KSPLIT];  // 25 MB
__device__ __align__(128) float g_trans[(size_t)MM * NN];            // 1.07 GB

// ---------------------------------------------------------------------------
// PTX helpers (sm_80-class only — harness ptxas targets base sm_103)
// ---------------------------------------------------------------------------
__device__ __forceinline__ uint32_t smem_u32(const void* p) {
    uint32_t a;
    asm("{ .reg .u64 t; cvta.to.shared.u64 t, %1; cvt.u32.u64 %0, t; }" : "=r"(a) : "l"(p));
    return a;
}
__device__ __forceinline__ void cp16(uint32_t dst, const void* src) {
    asm volatile("cp.async.cg.shared.global [%0], [%1], 16;" :: "r"(dst), "l"(src) : "memory");
}
__device__ __forceinline__ void cp_commit() {
    asm volatile("cp.async.commit_group;" ::: "memory");
}
template <int N>
__device__ __forceinline__ void cp_wait() {
    asm volatile("cp.async.wait_group %0;" :: "n"(N) : "memory");
}
__device__ __forceinline__ void ldsm4(uint32_t* r, uint32_t addr) {
    asm volatile("ldmatrix.sync.aligned.m8n8.x4.shared.b16 {%0,%1,%2,%3}, [%4];"
                 : "=r"(r[0]), "=r"(r[1]), "=r"(r[2]), "=r"(r[3]) : "r"(addr));
}
__device__ __forceinline__ void mma_bf16(float* d, const uint32_t* a, const uint32_t* b) {
    asm volatile(
        "mma.sync.aligned.m16n8k16.row.col.f32.bf16.bf16.f32 "
        "{%0,%1,%2,%3}, {%4,%5,%6,%7}, {%8,%9}, {%0,%1,%2,%3};"
        : "+f"(d[0]), "+f"(d[1]), "+f"(d[2]), "+f"(d[3])
        : "r"(a[0]), "r"(a[1]), "r"(a[2]), "r"(a[3]), "r"(b[0]), "r"(b[1]));
}
// SW128 swizzle, closed form for row*128+kb (kb < 128)
__device__ __forceinline__ uint32_t swoff(uint32_t row, uint32_t kb) {
    return row * 128u + (kb ^ ((row & 7u) << 4));
}

// ---------------------------------------------------------------------------
// Kernel 1: h = relu(actions@w1+b1); write A2 = [hi | hi | lo] bf16 rows
// ---------------------------------------------------------------------------
__global__ __launch_bounds__(256) void mlp1_kernel(const float* __restrict__ actions,
                                                   const float* __restrict__ w1,
                                                   const float* __restrict__ b1)
{
    __shared__ float as[8][AA];
    const int tid = threadIdx.x;
    const int m0 = blockIdx.x * 8;

    for (int i = tid; i < 8 * AA; i += 256)
        as[i >> 6][i & 63] = actions[(size_t)m0 * AA + i];
    __syncthreads();

    const int n = tid;
    float bv = b1[n];
    float acc[8];
#pragma unroll
    for (int r = 0; r < 8; r++) acc[r] = bv;
#pragma unroll 8
    for (int a = 0; a < AA; a++) {
        float w = w1[(size_t)a * HH + n];
#pragma unroll
        for (int r = 0; r < 8; r++) acc[r] = fmaf(as[r][a], w, acc[r]);
    }
#pragma unroll
    for (int r = 0; r < 8; r++) {
        float v = fmaxf(acc[r], 0.0f);
        __nv_bfloat16 hi = __float2bfloat16_rn(v);
        __nv_bfloat16 lo = __float2bfloat16_rn(v - __bfloat162float(hi));
        size_t row = (size_t)(m0 + r) * KSPLIT;
        g_A2[row + n] = hi;
        g_A2[row + KK + n] = hi;
        g_A2[row + 2 * KK + n] = lo;
    }
}

// ---------------------------------------------------------------------------
// Kernel 1b: B2T[n, :] = [hi(w2[:,n]) | lo(w2[:,n]) | hi(w2[:,n])]  (transpose)
// ---------------------------------------------------------------------------
__global__ __launch_bounds__(256) void bprep_kernel(const float* __restrict__ w2)
{
    __shared__ float tile[32][33];
    const int tx = threadIdx.x;          // 0..31
    const int ty = threadIdx.y;          // 0..7
    const int n0 = blockIdx.x * 32;
    const int k0 = blockIdx.y * 32;
#pragma unroll
    for (int i = 0; i < 4; i++) {
        int k = k0 + ty + i * 8;
        tile[ty + i * 8][tx] = w2[(size_t)k * NN + n0 + tx];
    }
    __syncthreads();
#pragma unroll
    for (int i = 0; i < 4; i++) {
        int nrow = ty + i * 8;
        float v = tile[tx][nrow];        // w2[k0+tx, n0+nrow]
        __nv_bfloat16 hi = __float2bfloat16_rn(v);
        __nv_bfloat16 lo = __float2bfloat16_rn(v - __bfloat162float(hi));
        size_t row = (size_t)(n0 + nrow) * KSPLIT + k0 + tx;
        g_B2T[row] = hi;
        g_B2T[row + KK] = lo;
        g_B2T[row + 2 * KK] = hi;
    }
}

// ---------------------------------------------------------------------------
// Kernel 2: bf16 mma.sync GEMM  trans = A2 @ B2T^T + b2
// BM=256, BN=128, BK=64 (128B rows, SW128), 3-stage cp.async.
// 512 threads = 16 warps in a 4x4 grid, warp tile 64x32 (4 warps per SMSP
// to saturate the HMMA pipe through LDSM/sync gaps).
// ---------------------------------------------------------------------------
#define BMG 256
#define BNG 128
#define BKG 64
#define NKT (KSPLIT/BKG)     // 12
#define NSTG 3
#define A_BYTES (BMG*128)    // 32768
#define B_BYTES (BNG*128)    // 16384
#define STAGE_BYTES (A_BYTES + B_BYTES)  // 49152

__global__ __launch_bounds__(512, 1) void gemm4_kernel(const float* __restrict__ bias)
{
    extern __shared__ char dsm[];
    __shared__ float bias_s[BNG];

    const uint32_t dyn = smem_u32(dsm);
    const int tid = threadIdx.x;
    const int wid = tid >> 5;
    const int lane = tid & 31;
    const int m0 = blockIdx.y * BMG;
    const int n0 = blockIdx.x * BNG;

    if (tid < BNG) bias_s[tid] = bias[n0 + tid];

    const char* Abase = (const char*)g_A2;
    const char* Bbase = (const char*)g_B2T;

    auto load_stage = [&](int s, int kt) {
        uint32_t sb = dyn + s * STAGE_BYTES;
        size_t kbyte = (size_t)kt * (BKG * 2);   // 128 B per k-tile
#pragma unroll
        for (int i = 0; i < 4; i++) {            // A: 2048 chunks of 16B
            int q = i * 512 + tid;
            uint32_t r = q >> 3, c = (q & 7) * 16;
            cp16(sb + swoff(r, c),
                 Abase + (size_t)(m0 + r) * (KSPLIT * 2) + kbyte + c);
        }
#pragma unroll
        for (int i = 0; i < 2; i++) {            // B: 1024 chunks
            int q = i * 512 + tid;
            uint32_t r = q >> 3, c = (q & 7) * 16;
            cp16(sb + A_BYTES + swoff(r, c),
                 Bbase + (size_t)(n0 + r) * (KSPLIT * 2) + kbyte + c);
        }
        cp_commit();
    };

    // prologue: 2 stages in flight
    load_stage(0, 0);
    load_stage(1, 1);

    // warp tiling: 4 (m) x 4 (n) warps, each 64x32
    const int m_w = (wid >> 2) * 64;
    const int n_w = (wid & 3) * 32;

    // per-lane ldmatrix row/kb components
    const uint32_t a_row = m_w + (lane & 7) + (lane & 8);          // + mi*16
    const uint32_t a_kb  = (lane >> 4) << 4;                       // + ks*32
    const uint32_t b_row = n_w + (lane & 7) + ((lane >> 4) << 3);  // + nj*16
    const uint32_t b_kb  = (lane & 8) << 1;                        // + ks*32

    float acc[4][4][4];
#pragma unroll
    for (int mi = 0; mi < 4; mi++)
#pragma unroll
        for (int nt = 0; nt < 4; nt++)
#pragma unroll
            for (int e = 0; e < 4; e++) acc[mi][nt][e] = 0.0f;

#pragma unroll 1
    for (int kt = 0; kt < NKT; kt++) {
        const int s = kt % NSTG;
        if (kt + 2 < NKT) load_stage((kt + 2) % NSTG, kt + 2);

        if (kt + 2 < NKT)      cp_wait<2>();
        else if (kt + 1 < NKT) cp_wait<1>();
        else                   cp_wait<0>();
        __syncthreads();

        const uint32_t abase = dyn + s * STAGE_BYTES;
        const uint32_t bbase = abase + A_BYTES;

#pragma unroll
        for (int ks = 0; ks < 4; ks++) {
            uint32_t af[4][4], bf[2][4];
#pragma unroll
            for (int mi = 0; mi < 4; mi++)
                ldsm4(af[mi], abase + swoff(a_row + mi * 16, a_kb + ks * 32));
#pragma unroll
            for (int nj = 0; nj < 2; nj++)
                ldsm4(bf[nj], bbase + swoff(b_row + nj * 16, b_kb + ks * 32));
#pragma unroll
            for (int mi = 0; mi < 4; mi++)
#pragma unroll
                for (int nj = 0; nj < 2; nj++) {
                    mma_bf16(acc[mi][2 * nj],     af[mi], &bf[nj][0]);
                    mma_bf16(acc[mi][2 * nj + 1], af[mi], &bf[nj][2]);
                }
        }
        __syncthreads();   // all warps done reading stage s before reload
    }

    // epilogue: direct float2 stores with bias
    const int cl = 2 * (lane & 3);
    const int rl = lane >> 2;
#pragma unroll
    for (int mi = 0; mi < 4; mi++) {
        int row0 = m0 + m_w + mi * 16 + rl;
#pragma unroll
        for (int nt = 0; nt < 4; nt++) {
            int lc = n_w + nt * 8 + cl;
            int col = n0 + lc;
            float bx = bias_s[lc], by = bias_s[lc + 1];
            float2 v0 = {acc[mi][nt][0] + bx, acc[mi][nt][1] + by};
            float2 v1 = {acc[mi][nt][2] + bx, acc[mi][nt][3] + by};
            *(float2*)(g_trans + (size_t)row0 * NN + col) = v0;
            *(float2*)(g_trans + (size_t)(row0 + 8) * NN + col) = v1;
        }
    }
}

// ---------------------------------------------------------------------------
// Kernel 3: sequential scan with register prefetch of T(t+1).
// One CTA per batch, 512 threads; c=tid>>5 picks 8-row chunk, (tid&31)*4 cols.
// ---------------------------------------------------------------------------
__global__ __launch_bounds__(512) void scan_kernel(const float* __restrict__ init_s,
                                                   float* __restrict__ out)
{
    __shared__ float s_sm[DD];
    __shared__ float red[16][DD];
    __shared__ float wsum[16];
    __shared__ float inv_sm;

    const int tid = threadIdx.x;
    const int b = blockIdx.x;

    if (tid < DD) {
        float v = init_s[tid];
        s_sm[tid] = v;
        red[0][tid] = v * v;
    }
    __syncthreads();
    if (tid == 0) {
        float s = 0.0f;
        for (int i = 0; i < DD; i++) s += red[0][i];
        inv_sm = 1.0f / fmaxf(sqrtf(s), 1e-12f);
    }
    __syncthreads();
    if (tid < DD) s_sm[tid] *= inv_sm;
    __syncthreads();

    const int c = tid >> 5;
    const int j = (tid & 31) * 4;
    const float* Tb = g_trans + (size_t)b * TT * (DD * DD);

    // prefetch T(0)
    float4 cur[8];
#pragma unroll
    for (int ii = 0; ii < 8; ii++)
        cur[ii] = *(const float4*)(Tb + (size_t)(c * 8 + ii) * DD + j);

    for (int t = 0; t < TT; t++) {
        // issue prefetch of T(t+1) first (no dependency -> overlaps compute)
        float4 nxt[8];
        if (t + 1 < TT) {
            const float* Tn = Tb + (size_t)(t + 1) * (DD * DD);
#pragma unroll
            for (int ii = 0; ii < 8; ii++)
                nxt[ii] = *(const float4*)(Tn + (size_t)(c * 8 + ii) * DD + j);
        }

        float4 p = {0.0f, 0.0f, 0.0f, 0.0f};
#pragma unroll
        for (int ii = 0; ii < 8; ii++) {
            float sv = s_sm[c * 8 + ii];
            p.x = fmaf(sv, cur[ii].x, p.x);
            p.y = fmaf(sv, cur[ii].y, p.y);
            p.z = fmaf(sv, cur[ii].z, p.z);
            p.w = fmaf(sv, cur[ii].w, p.w);
        }
        *(float4*)&red[c][j] = p;
        __syncthreads();

        float v = 0.0f, sq = 0.0f;
        if (tid < DD) {
#pragma unroll
            for (int cc = 0; cc < 16; cc++) v += red[cc][tid];
            v = fmaxf(v, 0.0f);
            sq = v * v;
        }
#pragma unroll
        for (int o = 16; o; o >>= 1) sq += __shfl_xor_sync(0xffffffffu, sq, o);
        if ((tid & 31) == 0) wsum[tid >> 5] = sq;
        __syncthreads();
        if (tid == 0) {
            float s = wsum[0] + wsum[1] + wsum[2] + wsum[3];
            inv_sm = 1.0f / fmaxf(sqrtf(s), 1e-12f);
        }
        __syncthreads();
        if (tid < DD) {
            float sn = v * inv_sm;
            s_sm[tid] = sn;
            out[((size_t)b * TT + t) * DD + tid] = sn;
        }
        __syncthreads();

#pragma unroll
        for (int ii = 0; ii < 8; ii++) cur[ii] = nxt[ii];
    }
}

// ---------------------------------------------------------------------------
extern "C" void kernel_launch(void* const* d_in, const int* in_sizes, int n_in,
                              void* d_out, int out_size)
{
    const float* actions = (const float*)d_in[0];
    const float* init_s  = (const float*)d_in[1];
    const float* w1      = (const float*)d_in[2];
    const float* b1      = (const float*)d_in[3];
    const float* w2      = (const float*)d_in[4];
    const float* b2      = (const float*)d_in[5];
    float* out = (float*)d_out;

    cudaFuncSetAttribute(gemm4_kernel, cudaFuncAttributeMaxDynamicSharedMemorySize,
                         NSTG * STAGE_BYTES);

    mlp1_kernel<<<MM / 8, 256>>>(actions, w1, b1);
    bprep_kernel<<<dim3(NN / 32, KK / 32), dim3(32, 8)>>>(w2);
    gemm4_kernel<<<dim3(NN / BNG, MM / BMG), 512, NSTG * STAGE_BYTES>>>(b2);
    scan_kernel<<<BB, 512>>>(init_s, out);
}